// round 2
// baseline (speedup 1.0000x reference)
#include <cuda_runtime.h>
#include <math.h>

#define S_LEN 2048
#define R_LEN 384
#define D_LEN 64

// attention output o (already softmax-normalized), per r: [R][64], j = h*8+c
__device__ float g_o[R_LEN * 64];

// Butterfly reduce-scatter: each lane holds v[32]; afterwards lane l holds
// sum over lanes of v_lane[l]. Destroys v. 31 shuffles.
__device__ __forceinline__ float bf_reduce32(float* v, int lane) {
#pragma unroll
    for (int m = 16; m >= 1; m >>= 1) {
        const bool hi = (lane & m) != 0;
#pragma unroll
        for (int i = 0; i < m; i++) {
            float send = hi ? v[i] : v[i + m];
            float recv = __shfl_xor_sync(0xffffffffu, send, m);
            float keep = hi ? v[i + m] : v[i];
            v[i] = keep + recv;
        }
    }
    return v[0];
}

// ---------------------------------------------------------------------------
// Kernel 1: one block per residue r. Computes LN on the fly, k/v into smem,
// masked pooled query, q = qavg@Wq, logits, softmax, o -> g_o[r].
// ---------------------------------------------------------------------------
extern __shared__ char smem_raw[];

__global__ void __launch_bounds__(256) attn_kernel(
    const float* __restrict__ M, const float* __restrict__ mask,
    const float* __restrict__ lng, const float* __restrict__ lnb,
    const float* __restrict__ Wq, const float* __restrict__ Wk,
    const float* __restrict__ Wv)
{
    float* kT    = (float*)smem_raw;          // [8][2048] -> later logits [8][2048]
    float* vT    = kT + 8 * S_LEN;            // [8][2048]
    float* bia   = vT + 8 * S_LEN;            // [2048]
    float* qws   = bia + S_LEN;               // [8][64] warp partials (q, then o)
    float* wk_s  = qws + 8 * 64;              // [64][8]
    float* wv_s  = wk_s + 512;                // [64][8]
    float* lng_s = wv_s + 512;                // 64
    float* lnb_s = lng_s + 64;                // 64
    float* q_s   = lnb_s + 64;                // 64
    float* qavg  = q_s + 64;                  // 64
    float* wred  = qavg + 64;                 // [8][8] warp max / sum partials
    float* fmax_s = wred + 64;                // 8
    float* fsum_s = fmax_s + 8;               // 8
    float* cred  = fsum_s + 8;                // 8

    const int tid = threadIdx.x;
    const int lane = tid & 31;
    const int w = tid >> 5;
    const int r = blockIdx.x;

    for (int i = tid; i < 512; i += 256) { wk_s[i] = Wk[i]; wv_s[i] = Wv[i]; }
    if (tid < 64) { lng_s[tid] = lng[tid]; lnb_s[tid] = lnb[tid]; }
    __syncthreads();

    float qa0 = 0.f, qa1 = 0.f, cntp = 0.f;

    // ---- pass A: LN, k, v, masked query accumulation -----------------------
    for (int it = 0; it < 8; it++) {
        const int s = it * 256 + tid;
        const float4* row = (const float4*)(M + ((size_t)s * R_LEN + r) * 64);

        float sum = 0.f, sq = 0.f;
#pragma unroll
        for (int i = 0; i < 16; i++) {
            float4 t = row[i];
            sum += t.x + t.y + t.z + t.w;
            sq  += t.x * t.x + t.y * t.y + t.z * t.z + t.w * t.w;
        }
        const float mu = sum * (1.f / 64.f);
        const float var = sq * (1.f / 64.f) - mu * mu;
        const float rs = rsqrtf(var + 1e-5f);

        float kk[8], vv[8];
#pragma unroll
        for (int c = 0; c < 8; c++) { kk[c] = 0.f; vv[c] = 0.f; }
#pragma unroll 4
        for (int i = 0; i < 16; i++) {
            float4 t = row[i];
#pragma unroll
            for (int kq = 0; kq < 4; kq++) {
                const int d = 4 * i + kq;
                float val = (kq == 0) ? t.x : (kq == 1) ? t.y : (kq == 2) ? t.z : t.w;
                float nd = (val - mu) * rs * lng_s[d] + lnb_s[d];
                const float4* a = (const float4*)(wk_s + d * 8);
                const float4* b = (const float4*)(wv_s + d * 8);
                float4 a0 = a[0], a1 = a[1], b0 = b[0], b1 = b[1];
                kk[0] = fmaf(nd, a0.x, kk[0]); kk[1] = fmaf(nd, a0.y, kk[1]);
                kk[2] = fmaf(nd, a0.z, kk[2]); kk[3] = fmaf(nd, a0.w, kk[3]);
                kk[4] = fmaf(nd, a1.x, kk[4]); kk[5] = fmaf(nd, a1.y, kk[5]);
                kk[6] = fmaf(nd, a1.z, kk[6]); kk[7] = fmaf(nd, a1.w, kk[7]);
                vv[0] = fmaf(nd, b0.x, vv[0]); vv[1] = fmaf(nd, b0.y, vv[1]);
                vv[2] = fmaf(nd, b0.z, vv[2]); vv[3] = fmaf(nd, b0.w, vv[3]);
                vv[4] = fmaf(nd, b1.x, vv[4]); vv[5] = fmaf(nd, b1.y, vv[5]);
                vv[6] = fmaf(nd, b1.z, vv[6]); vv[7] = fmaf(nd, b1.w, vv[7]);
            }
        }
#pragma unroll
        for (int c = 0; c < 8; c++) { kT[c * S_LEN + s] = kk[c]; vT[c * S_LEN + s] = vv[c]; }

        const float mk = mask[(size_t)s * R_LEN + r];
        bia[s] = 1e9f * (mk - 1.f);
        cntp += mk;

        // masked normalized values -> butterfly reduce (two 32-blocks)
#pragma unroll
        for (int half = 0; half < 2; half++) {
            float p[32];
#pragma unroll
            for (int i = 0; i < 8; i++) {
                float4 t = row[half * 8 + i];
                const int d = half * 32 + 4 * i;
                p[4 * i + 0] = mk * ((t.x - mu) * rs * lng_s[d + 0] + lnb_s[d + 0]);
                p[4 * i + 1] = mk * ((t.y - mu) * rs * lng_s[d + 1] + lnb_s[d + 1]);
                p[4 * i + 2] = mk * ((t.z - mu) * rs * lng_s[d + 2] + lnb_s[d + 2]);
                p[4 * i + 3] = mk * ((t.w - mu) * rs * lng_s[d + 3] + lnb_s[d + 3]);
            }
            float red = bf_reduce32(p, lane);
            if (half == 0) qa0 += red; else qa1 += red;
        }
    }

    qws[w * 64 + lane]      = qa0;   // d = lane
    qws[w * 64 + 32 + lane] = qa1;   // d = 32 + lane
    float cw = cntp;
#pragma unroll
    for (int o = 16; o >= 1; o >>= 1) cw += __shfl_xor_sync(0xffffffffu, cw, o);
    if (lane == 0) cred[w] = cw;
    __syncthreads();

    if (tid < 64) {
        float qs = 0.f;
#pragma unroll
        for (int ww = 0; ww < 8; ww++) qs += qws[ww * 64 + tid];
        float cnt = cred[0] + cred[1] + cred[2] + cred[3] +
                    cred[4] + cred[5] + cred[6] + cred[7];
        qavg[tid] = qs / (cnt + 1e-10f);
    }
    __syncthreads();
    if (tid < 64) {
        float a = 0.f;
#pragma unroll
        for (int d = 0; d < 64; d++) a = fmaf(qavg[d], Wq[d * 64 + tid], a);
        q_s[tid] = a * 0.35355339059327373f;  // * C^-0.5
    }
    __syncthreads();

    // ---- pass B: logits (overwrite kT) + per-head max ----------------------
    float mx[8];
#pragma unroll
    for (int h = 0; h < 8; h++) mx[h] = -1e30f;
    for (int it = 0; it < 8; it++) {
        const int s = it * 256 + tid;
        float kv[8];
#pragma unroll
        for (int c = 0; c < 8; c++) kv[c] = kT[c * S_LEN + s];
        const float b = bia[s];
#pragma unroll
        for (int h = 0; h < 8; h++) {
            float l = b;
#pragma unroll
            for (int c = 0; c < 8; c++) l = fmaf(q_s[h * 8 + c], kv[c], l);
            kT[h * S_LEN + s] = l;
            mx[h] = fmaxf(mx[h], l);
        }
    }
#pragma unroll
    for (int h = 0; h < 8; h++) {
#pragma unroll
        for (int o = 16; o >= 1; o >>= 1)
            mx[h] = fmaxf(mx[h], __shfl_xor_sync(0xffffffffu, mx[h], o));
    }
    if (lane == 0) {
#pragma unroll
        for (int h = 0; h < 8; h++) wred[w * 8 + h] = mx[h];
    }
    __syncthreads();
    if (tid < 8) {
        float m0 = wred[tid];
#pragma unroll
        for (int ww = 1; ww < 8; ww++) m0 = fmaxf(m0, wred[ww * 8 + tid]);
        fmax_s[tid] = m0;
    }
    __syncthreads();

    // ---- pass C: exp, sum, o accumulation ----------------------------------
    float fm[8];
#pragma unroll
    for (int h = 0; h < 8; h++) fm[h] = fmax_s[h];
    float sacc[8], oacc[64];
#pragma unroll
    for (int h = 0; h < 8; h++) sacc[h] = 0.f;
#pragma unroll
    for (int j = 0; j < 64; j++) oacc[j] = 0.f;

    for (int it = 0; it < 8; it++) {
        const int s = it * 256 + tid;
        float e[8];
#pragma unroll
        for (int h = 0; h < 8; h++) {
            e[h] = __expf(kT[h * S_LEN + s] - fm[h]);
            sacc[h] += e[h];
        }
        float vv2[8];
#pragma unroll
        for (int c = 0; c < 8; c++) vv2[c] = vT[c * S_LEN + s];
#pragma unroll
        for (int h = 0; h < 8; h++)
#pragma unroll
            for (int c = 0; c < 8; c++)
                oacc[h * 8 + c] = fmaf(e[h], vv2[c], oacc[h * 8 + c]);
    }
#pragma unroll
    for (int h = 0; h < 8; h++) {
#pragma unroll
        for (int o = 16; o >= 1; o >>= 1)
            sacc[h] += __shfl_xor_sync(0xffffffffu, sacc[h], o);
    }
    if (lane == 0) {
#pragma unroll
        for (int h = 0; h < 8; h++) wred[w * 8 + h] = sacc[h];
    }
    // butterfly the o accumulators: lane gets j=lane and j=32+lane
    float o0 = bf_reduce32(oacc, lane);
    float o1 = bf_reduce32(oacc + 32, lane);
    qws[w * 64 + lane] = o0;
    qws[w * 64 + 32 + lane] = o1;
    __syncthreads();
    if (tid < 8) {
        float ss = 0.f;
#pragma unroll
        for (int ww = 0; ww < 8; ww++) ss += wred[ww * 8 + tid];
        fsum_s[tid] = ss;
    }
    __syncthreads();
    if (tid < 64) {
        float t = 0.f;
#pragma unroll
        for (int ww = 0; ww < 8; ww++) t += qws[ww * 64 + tid];
        g_o[r * 64 + tid] = t / fsum_s[tid >> 3];
    }
}

// ---------------------------------------------------------------------------
// Kernel 2: per (s,r) row: LN (recomputed), x = n@Wg, g = sigmoid(x+bg)*o[r],
// out = M_raw + g@Wo + bo. One thread per row; weights in smem (broadcast).
// ---------------------------------------------------------------------------
__global__ void __launch_bounds__(256) out_kernel(
    const float* __restrict__ M,
    const float* __restrict__ lng, const float* __restrict__ lnb,
    const float* __restrict__ Wg, const float* __restrict__ bg,
    const float* __restrict__ Wo, const float* __restrict__ bo,
    float* __restrict__ out)
{
    __shared__ float wg_s[4096];   // [d][j]
    __shared__ float woT_s[4096];  // [d][j] = Wo[j][d]
    __shared__ float o_s[64], bg_s[64], bo_s[64], lng_s[64], lnb_s[64];

    const int tid = threadIdx.x;
    const int r = blockIdx.y;

    for (int i = tid; i < 4096; i += 256) {
        wg_s[i] = Wg[i];
        int j = i >> 6, d = i & 63;
        woT_s[d * 64 + j] = Wo[i];
    }
    if (tid < 64) {
        o_s[tid] = g_o[r * 64 + tid];
        bg_s[tid] = bg[tid];
        bo_s[tid] = bo[tid];
        lng_s[tid] = lng[tid];
        lnb_s[tid] = lnb[tid];
    }
    __syncthreads();

    const int s = blockIdx.x * 256 + tid;
    const size_t base = ((size_t)s * R_LEN + r) * 64;
    const float4* row = (const float4*)(M + base);

    float sum = 0.f, sq = 0.f;
#pragma unroll
    for (int i = 0; i < 16; i++) {
        float4 t = row[i];
        sum += t.x + t.y + t.z + t.w;
        sq  += t.x * t.x + t.y * t.y + t.z * t.z + t.w * t.w;
    }
    const float mu = sum * (1.f / 64.f);
    const float rs = rsqrtf(sq * (1.f / 64.f) - mu * mu + 1e-5f);

    float x[64];
#pragma unroll
    for (int j = 0; j < 64; j++) x[j] = 0.f;

#pragma unroll 1
    for (int i = 0; i < 16; i++) {
        float4 t = row[i];
#pragma unroll
        for (int kq = 0; kq < 4; kq++) {
            const int d = 4 * i + kq;
            float val = (kq == 0) ? t.x : (kq == 1) ? t.y : (kq == 2) ? t.z : t.w;
            float nd = (val - mu) * rs * lng_s[d] + lnb_s[d];
            const float4* wg = (const float4*)(wg_s + d * 64);
#pragma unroll
            for (int j4 = 0; j4 < 16; j4++) {
                float4 ww = wg[j4];
                x[4 * j4 + 0] = fmaf(nd, ww.x, x[4 * j4 + 0]);
                x[4 * j4 + 1] = fmaf(nd, ww.y, x[4 * j4 + 1]);
                x[4 * j4 + 2] = fmaf(nd, ww.z, x[4 * j4 + 2]);
                x[4 * j4 + 3] = fmaf(nd, ww.w, x[4 * j4 + 3]);
            }
        }
    }

#pragma unroll
    for (int j = 0; j < 64; j++) {
        float t = x[j] + bg_s[j];
        float gg = __fdividef(1.f, 1.f + __expf(-t));
        x[j] = gg * o_s[j];
    }

    float* op = out + base;
#pragma unroll 1
    for (int i = 0; i < 16; i++) {
        float4 t = row[i];
        float resv[4];
#pragma unroll
        for (int kq = 0; kq < 4; kq++) {
            const int d = 4 * i + kq;
            float acc = bo_s[d];
            const float4* wo = (const float4*)(woT_s + d * 64);
#pragma unroll
            for (int j4 = 0; j4 < 16; j4++) {
                float4 ww = wo[j4];
                acc = fmaf(x[4 * j4 + 0], ww.x, acc);
                acc = fmaf(x[4 * j4 + 1], ww.y, acc);
                acc = fmaf(x[4 * j4 + 2], ww.z, acc);
                acc = fmaf(x[4 * j4 + 3], ww.w, acc);
            }
            float mval = (kq == 0) ? t.x : (kq == 1) ? t.y : (kq == 2) ? t.z : t.w;
            resv[kq] = mval + acc;
        }
        ((float4*)op)[i] = make_float4(resv[0], resv[1], resv[2], resv[3]);
    }
}

// ---------------------------------------------------------------------------
extern "C" void kernel_launch(void* const* d_in, const int* in_sizes, int n_in,
                              void* d_out, int out_size)
{
    const float* M    = (const float*)d_in[0];
    const float* mask = (const float*)d_in[1];
    const float* lng  = (const float*)d_in[2];
    const float* lnb  = (const float*)d_in[3];
    const float* Wq   = (const float*)d_in[4];
    const float* Wk   = (const float*)d_in[5];
    const float* Wv   = (const float*)d_in[6];
    const float* Wg   = (const float*)d_in[7];
    const float* bg   = (const float*)d_in[8];
    const float* Wo   = (const float*)d_in[9];
    const float* bo   = (const float*)d_in[10];
    float* out = (float*)d_out;

    const size_t smem1 = (size_t)(16384 + 16384 + 2048 + 512 + 512 + 512 +
                                  64 + 64 + 64 + 64 + 64 + 8 + 8 + 8) * sizeof(float);
    cudaFuncSetAttribute(attn_kernel, cudaFuncAttributeMaxDynamicSharedMemorySize,
                         (int)smem1);

    attn_kernel<<<R_LEN, 256, smem1>>>(M, mask, lng, lnb, Wq, Wk, Wv);
    out_kernel<<<dim3(S_LEN / 256, R_LEN), 256>>>(M, lng, lnb, Wg, bg, Wo, bo, out);
}

// round 3
// speedup vs baseline: 1.4987x; 1.4987x over previous
#include <cuda_runtime.h>
#include <math.h>

#define S_LEN 2048
#define R_LEN 384
#define D_LEN 64

// attention output o (already softmax-normalized), per r: [R][64], j = h*8+c
__device__ float g_o[R_LEN * 64];

#define FMA2(d, a, b) asm("fma.rn.f32x2 %0, %1, %2, %0;" : "+l"(d) : "l"(a), "l"(b))
#define PACKDUP(d, x) asm("mov.b64 %0, {%1, %1};" : "=l"(d) : "r"(__float_as_uint(x)))
#define UNPACK2(lo, hi, v) asm("mov.b64 {%0, %1}, %2;" : "=r"(lo), "=r"(hi) : "l"(v))
#define PACK2(d, lo, hi) asm("mov.b64 %0, {%1, %2};" : "=l"(d) : "r"(__float_as_uint(lo)), "r"(__float_as_uint(hi)))

// Butterfly reduce-scatter: each lane holds v[32]; afterwards lane l holds
// sum over lanes of v_lane[l]. Destroys v. 31 shuffles.
__device__ __forceinline__ float bf_reduce32(float* v, int lane) {
#pragma unroll
    for (int m = 16; m >= 1; m >>= 1) {
        const bool hi = (lane & m) != 0;
#pragma unroll
        for (int i = 0; i < m; i++) {
            float send = hi ? v[i] : v[i + m];
            float recv = __shfl_xor_sync(0xffffffffu, send, m);
            float keep = hi ? v[i + m] : v[i];
            v[i] = keep + recv;
        }
    }
    return v[0];
}

// ---------------------------------------------------------------------------
// Kernel 1: one block per residue r (unchanged from R2).
// ---------------------------------------------------------------------------
extern __shared__ char smem_raw[];

__global__ void __launch_bounds__(256) attn_kernel(
    const float* __restrict__ M, const float* __restrict__ mask,
    const float* __restrict__ lng, const float* __restrict__ lnb,
    const float* __restrict__ Wq, const float* __restrict__ Wk,
    const float* __restrict__ Wv)
{
    float* kT    = (float*)smem_raw;          // [8][2048] -> later logits [8][2048]
    float* vT    = kT + 8 * S_LEN;            // [8][2048]
    float* bia   = vT + 8 * S_LEN;            // [2048]
    float* qws   = bia + S_LEN;               // [8][64] warp partials (q, then o)
    float* wk_s  = qws + 8 * 64;              // [64][8]
    float* wv_s  = wk_s + 512;                // [64][8]
    float* lng_s = wv_s + 512;                // 64
    float* lnb_s = lng_s + 64;                // 64
    float* q_s   = lnb_s + 64;                // 64
    float* qavg  = q_s + 64;                  // 64
    float* wred  = qavg + 64;                 // [8][8] warp max / sum partials
    float* fmax_s = wred + 64;                // 8
    float* fsum_s = fmax_s + 8;               // 8
    float* cred  = fsum_s + 8;                // 8

    const int tid = threadIdx.x;
    const int lane = tid & 31;
    const int w = tid >> 5;
    const int r = blockIdx.x;

    for (int i = tid; i < 512; i += 256) { wk_s[i] = Wk[i]; wv_s[i] = Wv[i]; }
    if (tid < 64) { lng_s[tid] = lng[tid]; lnb_s[tid] = lnb[tid]; }
    __syncthreads();

    float qa0 = 0.f, qa1 = 0.f, cntp = 0.f;

    // ---- pass A: LN, k, v, masked query accumulation -----------------------
    for (int it = 0; it < 8; it++) {
        const int s = it * 256 + tid;
        const float4* row = (const float4*)(M + ((size_t)s * R_LEN + r) * 64);

        float sum = 0.f, sq = 0.f;
#pragma unroll
        for (int i = 0; i < 16; i++) {
            float4 t = row[i];
            sum += t.x + t.y + t.z + t.w;
            sq  += t.x * t.x + t.y * t.y + t.z * t.z + t.w * t.w;
        }
        const float mu = sum * (1.f / 64.f);
        const float var = sq * (1.f / 64.f) - mu * mu;
        const float rs = rsqrtf(var + 1e-5f);

        float kk[8], vv[8];
#pragma unroll
        for (int c = 0; c < 8; c++) { kk[c] = 0.f; vv[c] = 0.f; }
#pragma unroll 4
        for (int i = 0; i < 16; i++) {
            float4 t = row[i];
#pragma unroll
            for (int kq = 0; kq < 4; kq++) {
                const int d = 4 * i + kq;
                float val = (kq == 0) ? t.x : (kq == 1) ? t.y : (kq == 2) ? t.z : t.w;
                float nd = (val - mu) * rs * lng_s[d] + lnb_s[d];
                const float4* a = (const float4*)(wk_s + d * 8);
                const float4* b = (const float4*)(wv_s + d * 8);
                float4 a0 = a[0], a1 = a[1], b0 = b[0], b1 = b[1];
                kk[0] = fmaf(nd, a0.x, kk[0]); kk[1] = fmaf(nd, a0.y, kk[1]);
                kk[2] = fmaf(nd, a0.z, kk[2]); kk[3] = fmaf(nd, a0.w, kk[3]);
                kk[4] = fmaf(nd, a1.x, kk[4]); kk[5] = fmaf(nd, a1.y, kk[5]);
                kk[6] = fmaf(nd, a1.z, kk[6]); kk[7] = fmaf(nd, a1.w, kk[7]);
                vv[0] = fmaf(nd, b0.x, vv[0]); vv[1] = fmaf(nd, b0.y, vv[1]);
                vv[2] = fmaf(nd, b0.z, vv[2]); vv[3] = fmaf(nd, b0.w, vv[3]);
                vv[4] = fmaf(nd, b1.x, vv[4]); vv[5] = fmaf(nd, b1.y, vv[5]);
                vv[6] = fmaf(nd, b1.z, vv[6]); vv[7] = fmaf(nd, b1.w, vv[7]);
            }
        }
#pragma unroll
        for (int c = 0; c < 8; c++) { kT[c * S_LEN + s] = kk[c]; vT[c * S_LEN + s] = vv[c]; }

        const float mk = mask[(size_t)s * R_LEN + r];
        bia[s] = 1e9f * (mk - 1.f);
        cntp += mk;

#pragma unroll
        for (int hlf = 0; hlf < 2; hlf++) {
            float p[32];
#pragma unroll
            for (int i = 0; i < 8; i++) {
                float4 t = row[hlf * 8 + i];
                const int d = hlf * 32 + 4 * i;
                p[4 * i + 0] = mk * ((t.x - mu) * rs * lng_s[d + 0] + lnb_s[d + 0]);
                p[4 * i + 1] = mk * ((t.y - mu) * rs * lng_s[d + 1] + lnb_s[d + 1]);
                p[4 * i + 2] = mk * ((t.z - mu) * rs * lng_s[d + 2] + lnb_s[d + 2]);
                p[4 * i + 3] = mk * ((t.w - mu) * rs * lng_s[d + 3] + lnb_s[d + 3]);
            }
            float red = bf_reduce32(p, lane);
            if (hlf == 0) qa0 += red; else qa1 += red;
        }
    }

    qws[w * 64 + lane]      = qa0;
    qws[w * 64 + 32 + lane] = qa1;
    float cw = cntp;
#pragma unroll
    for (int o = 16; o >= 1; o >>= 1) cw += __shfl_xor_sync(0xffffffffu, cw, o);
    if (lane == 0) cred[w] = cw;
    __syncthreads();

    if (tid < 64) {
        float qs = 0.f;
#pragma unroll
        for (int ww = 0; ww < 8; ww++) qs += qws[ww * 64 + tid];
        float cnt = cred[0] + cred[1] + cred[2] + cred[3] +
                    cred[4] + cred[5] + cred[6] + cred[7];
        qavg[tid] = qs / (cnt + 1e-10f);
    }
    __syncthreads();
    if (tid < 64) {
        float a = 0.f;
#pragma unroll
        for (int d = 0; d < 64; d++) a = fmaf(qavg[d], Wq[d * 64 + tid], a);
        q_s[tid] = a * 0.35355339059327373f;
    }
    __syncthreads();

    // ---- pass B: logits + per-head max ------------------------------------
    float mx[8];
#pragma unroll
    for (int h = 0; h < 8; h++) mx[h] = -1e30f;
    for (int it = 0; it < 8; it++) {
        const int s = it * 256 + tid;
        float kv[8];
#pragma unroll
        for (int c = 0; c < 8; c++) kv[c] = kT[c * S_LEN + s];
        const float b = bia[s];
#pragma unroll
        for (int h = 0; h < 8; h++) {
            float l = b;
#pragma unroll
            for (int c = 0; c < 8; c++) l = fmaf(q_s[h * 8 + c], kv[c], l);
            kT[h * S_LEN + s] = l;
            mx[h] = fmaxf(mx[h], l);
        }
    }
#pragma unroll
    for (int h = 0; h < 8; h++) {
#pragma unroll
        for (int o = 16; o >= 1; o >>= 1)
            mx[h] = fmaxf(mx[h], __shfl_xor_sync(0xffffffffu, mx[h], o));
    }
    if (lane == 0) {
#pragma unroll
        for (int h = 0; h < 8; h++) wred[w * 8 + h] = mx[h];
    }
    __syncthreads();
    if (tid < 8) {
        float m0 = wred[tid];
#pragma unroll
        for (int ww = 1; ww < 8; ww++) m0 = fmaxf(m0, wred[ww * 8 + tid]);
        fmax_s[tid] = m0;
    }
    __syncthreads();

    // ---- pass C: exp, sum, o accumulation ----------------------------------
    float fm[8];
#pragma unroll
    for (int h = 0; h < 8; h++) fm[h] = fmax_s[h];
    float sacc[8], oacc[64];
#pragma unroll
    for (int h = 0; h < 8; h++) sacc[h] = 0.f;
#pragma unroll
    for (int j = 0; j < 64; j++) oacc[j] = 0.f;

    for (int it = 0; it < 8; it++) {
        const int s = it * 256 + tid;
        float e[8];
#pragma unroll
        for (int h = 0; h < 8; h++) {
            e[h] = __expf(kT[h * S_LEN + s] - fm[h]);
            sacc[h] += e[h];
        }
        float vv2[8];
#pragma unroll
        for (int c = 0; c < 8; c++) vv2[c] = vT[c * S_LEN + s];
#pragma unroll
        for (int h = 0; h < 8; h++)
#pragma unroll
            for (int c = 0; c < 8; c++)
                oacc[h * 8 + c] = fmaf(e[h], vv2[c], oacc[h * 8 + c]);
    }
#pragma unroll
    for (int h = 0; h < 8; h++) {
#pragma unroll
        for (int o = 16; o >= 1; o >>= 1)
            sacc[h] += __shfl_xor_sync(0xffffffffu, sacc[h], o);
    }
    if (lane == 0) {
#pragma unroll
        for (int h = 0; h < 8; h++) wred[w * 8 + h] = sacc[h];
    }
    float o0 = bf_reduce32(oacc, lane);
    float o1 = bf_reduce32(oacc + 32, lane);
    qws[w * 64 + lane] = o0;
    qws[w * 64 + 32 + lane] = o1;
    __syncthreads();
    if (tid < 8) {
        float ss = 0.f;
#pragma unroll
        for (int ww = 0; ww < 8; ww++) ss += wred[ww * 8 + tid];
        fsum_s[tid] = ss;
    }
    __syncthreads();
    if (tid < 64) {
        float t = 0.f;
#pragma unroll
        for (int ww = 0; ww < 8; ww++) t += qws[ww * 64 + tid];
        g_o[r * 64 + tid] = t / fsum_s[tid >> 3];
    }
}

// ---------------------------------------------------------------------------
// Kernel 2 (rewritten): block = 128 consecutive r at fixed s. Register-blocked
// GEMMs with packed fp32x2 FMA. Thread grid 16 row-groups x 16 col-groups,
// 8 rows x 4 cols per thread (rows packed in pairs).
// ---------------------------------------------------------------------------
#define NT_STRIDE 132

__global__ void __launch_bounds__(256) out_kernel(
    const float* __restrict__ M,
    const float* __restrict__ lng, const float* __restrict__ lnb,
    const float* __restrict__ Wg, const float* __restrict__ bg,
    const float* __restrict__ Wo, const float* __restrict__ bo,
    float* __restrict__ out)
{
    extern __shared__ float sm[];
    float* Nt    = sm;                  // [64][132] normalized, transposed (later Gt)
    float* wg_s  = Nt + 64 * NT_STRIDE; // 4096
    float* wo_s  = wg_s + 4096;         // 4096
    float* psum  = wo_s + 4096;         // 256
    float* psq   = psum + 256;          // 256
    float* lng_s = psq + 256;           // 64
    float* lnb_s = lng_s + 64;          // 64
    float* bg_s  = lnb_s + 64;          // 64
    float* bo_s  = bg_s + 64;           // 64

    const int tid = threadIdx.x;
    const int r0 = blockIdx.x * 128;
    const int s  = blockIdx.y;
    const float* gbase = M + ((size_t)s * R_LEN + r0) * 64;

    for (int i = tid; i < 4096; i += 256) { wg_s[i] = Wg[i]; wo_s[i] = Wo[i]; }
    if (tid < 64) {
        lng_s[tid] = lng[tid]; lnb_s[tid] = lnb[tid];
        bg_s[tid] = bg[tid];   bo_s[tid] = bo[tid];
    }

    // ---- stage: LN stats + normalized transpose into Nt --------------------
    const int row = tid & 127;
    const int hf  = tid >> 7;           // which half of the 64 dims
    float4 rv[8];
    {
        const float4* src = (const float4*)(gbase + row * 64 + hf * 32);
#pragma unroll
        for (int i = 0; i < 8; i++) rv[i] = src[i];
        float sum = 0.f, sq = 0.f;
#pragma unroll
        for (int i = 0; i < 8; i++) {
            float4 t = rv[i];
            sum += t.x + t.y + t.z + t.w;
            sq  += t.x * t.x + t.y * t.y + t.z * t.z + t.w * t.w;
        }
        psum[hf * 128 + row] = sum;
        psq[hf * 128 + row]  = sq;
    }
    __syncthreads();
    {
        float sum = psum[row] + psum[128 + row];
        float sq  = psq[row] + psq[128 + row];
        float mu = sum * (1.f / 64.f);
        float rs = rsqrtf(sq * (1.f / 64.f) - mu * mu + 1e-5f);
#pragma unroll
        for (int i = 0; i < 8; i++) {
            float4 t = rv[i];
            int d = hf * 32 + 4 * i;
            Nt[(d + 0) * NT_STRIDE + row] = (t.x - mu) * rs * lng_s[d + 0] + lnb_s[d + 0];
            Nt[(d + 1) * NT_STRIDE + row] = (t.y - mu) * rs * lng_s[d + 1] + lnb_s[d + 1];
            Nt[(d + 2) * NT_STRIDE + row] = (t.z - mu) * rs * lng_s[d + 2] + lnb_s[d + 2];
            Nt[(d + 3) * NT_STRIDE + row] = (t.w - mu) * rs * lng_s[d + 3] + lnb_s[d + 3];
        }
    }
    __syncthreads();

    const int rg = tid >> 4;   // row group: rows rg*8 .. rg*8+7
    const int cg = tid & 15;   // col group: cols cg*4 .. cg*4+3

    unsigned long long acc[4][4];
#pragma unroll
    for (int p = 0; p < 4; p++)
#pragma unroll
        for (int c = 0; c < 4; c++) acc[p][c] = 0ull;

    // ---- GEMM1: X = N @ Wg --------------------------------------------------
#pragma unroll 16
    for (int k = 0; k < 64; k++) {
        const ulonglong2* ap = (const ulonglong2*)(Nt + k * NT_STRIDE + rg * 8);
        ulonglong2 A01 = ap[0];
        ulonglong2 A23 = ap[1];
        unsigned long long a[4] = {A01.x, A01.y, A23.x, A23.y};
        float4 bw = *(const float4*)(wg_s + k * 64 + cg * 4);
        unsigned long long b[4];
        PACKDUP(b[0], bw.x); PACKDUP(b[1], bw.y);
        PACKDUP(b[2], bw.z); PACKDUP(b[3], bw.w);
#pragma unroll
        for (int p = 0; p < 4; p++)
#pragma unroll
            for (int c = 0; c < 4; c++) FMA2(acc[p][c], a[p], b[c]);
    }

    // ---- gate: g = sigmoid(x + bg) * o ------------------------------------
    unsigned long long gpk[4][4];
#pragma unroll
    for (int p = 0; p < 4; p++) {
        const int rA = rg * 8 + 2 * p;
        float4 oA = *(const float4*)(g_o + (size_t)(r0 + rA) * 64 + cg * 4);
        float4 oB = *(const float4*)(g_o + (size_t)(r0 + rA + 1) * 64 + cg * 4);
#pragma unroll
        for (int c = 0; c < 4; c++) {
            unsigned int ulo, uhi;
            UNPACK2(ulo, uhi, acc[p][c]);
            float xb = bg_s[cg * 4 + c];
            float xa = __uint_as_float(ulo) + xb;
            float xbv = __uint_as_float(uhi) + xb;
            float ga = __fdividef(1.f, 1.f + __expf(-xa));
            float gb = __fdividef(1.f, 1.f + __expf(-xbv));
            float ov_a = (c == 0) ? oA.x : (c == 1) ? oA.y : (c == 2) ? oA.z : oA.w;
            float ov_b = (c == 0) ? oB.x : (c == 1) ? oB.y : (c == 2) ? oB.z : oB.w;
            PACK2(gpk[p][c], ga * ov_a, gb * ov_b);
        }
    }
    __syncthreads();   // everyone done reading Nt

    // store G transposed into Nt (now Gt[j][row]), row pairs as b64
#pragma unroll
    for (int c = 0; c < 4; c++) {
        const int j = cg * 4 + c;
#pragma unroll
        for (int p = 0; p < 4; p++) {
            *(unsigned long long*)(Nt + j * NT_STRIDE + rg * 8 + 2 * p) = gpk[p][c];
        }
    }
    __syncthreads();

    // ---- GEMM2: OUT = G @ Wo -----------------------------------------------
#pragma unroll
    for (int p = 0; p < 4; p++)
#pragma unroll
        for (int c = 0; c < 4; c++) acc[p][c] = 0ull;

#pragma unroll 16
    for (int k = 0; k < 64; k++) {
        const ulonglong2* ap = (const ulonglong2*)(Nt + k * NT_STRIDE + rg * 8);
        ulonglong2 A01 = ap[0];
        ulonglong2 A23 = ap[1];
        unsigned long long a[4] = {A01.x, A01.y, A23.x, A23.y};
        float4 bw = *(const float4*)(wo_s + k * 64 + cg * 4);
        unsigned long long b[4];
        PACKDUP(b[0], bw.x); PACKDUP(b[1], bw.y);
        PACKDUP(b[2], bw.z); PACKDUP(b[3], bw.w);
#pragma unroll
        for (int p = 0; p < 4; p++)
#pragma unroll
            for (int c = 0; c < 4; c++) FMA2(acc[p][c], a[p], b[c]);
    }

    // ---- epilogue: residual + bo, store ------------------------------------
    float* obase = out + ((size_t)s * R_LEN + r0) * 64;
    const float bo0 = bo_s[cg * 4 + 0], bo1 = bo_s[cg * 4 + 1];
    const float bo2 = bo_s[cg * 4 + 2], bo3 = bo_s[cg * 4 + 3];
#pragma unroll
    for (int p = 0; p < 4; p++) {
        const int rA = rg * 8 + 2 * p;
        float4 mA = *(const float4*)(gbase + rA * 64 + cg * 4);
        float4 mB = *(const float4*)(gbase + (rA + 1) * 64 + cg * 4);
        unsigned int lo0, hi0, lo1, hi1, lo2, hi2, lo3, hi3;
        UNPACK2(lo0, hi0, acc[p][0]);
        UNPACK2(lo1, hi1, acc[p][1]);
        UNPACK2(lo2, hi2, acc[p][2]);
        UNPACK2(lo3, hi3, acc[p][3]);
        float4 ra, rb;
        ra.x = mA.x + __uint_as_float(lo0) + bo0;
        ra.y = mA.y + __uint_as_float(lo1) + bo1;
        ra.z = mA.z + __uint_as_float(lo2) + bo2;
        ra.w = mA.w + __uint_as_float(lo3) + bo3;
        rb.x = mB.x + __uint_as_float(hi0) + bo0;
        rb.y = mB.y + __uint_as_float(hi1) + bo1;
        rb.z = mB.z + __uint_as_float(hi2) + bo2;
        rb.w = mB.w + __uint_as_float(hi3) + bo3;
        *(float4*)(obase + rA * 64 + cg * 4) = ra;
        *(float4*)(obase + (rA + 1) * 64 + cg * 4) = rb;
    }
}

// ---------------------------------------------------------------------------
extern "C" void kernel_launch(void* const* d_in, const int* in_sizes, int n_in,
                              void* d_out, int out_size)
{
    const float* M    = (const float*)d_in[0];
    const float* mask = (const float*)d_in[1];
    const float* lng  = (const float*)d_in[2];
    const float* lnb  = (const float*)d_in[3];
    const float* Wq   = (const float*)d_in[4];
    const float* Wk   = (const float*)d_in[5];
    const float* Wv   = (const float*)d_in[6];
    const float* Wg   = (const float*)d_in[7];
    const float* bg   = (const float*)d_in[8];
    const float* Wo   = (const float*)d_in[9];
    const float* bo   = (const float*)d_in[10];
    float* out = (float*)d_out;

    const size_t smem1 = (size_t)(16384 + 16384 + 2048 + 512 + 512 + 512 +
                                  64 + 64 + 64 + 64 + 64 + 8 + 8 + 8) * sizeof(float);
    cudaFuncSetAttribute(attn_kernel, cudaFuncAttributeMaxDynamicSharedMemorySize,
                         (int)smem1);

    const size_t smem2 = (size_t)(64 * NT_STRIDE + 4096 + 4096 + 256 + 256 +
                                  4 * 64) * sizeof(float);
    cudaFuncSetAttribute(out_kernel, cudaFuncAttributeMaxDynamicSharedMemorySize,
                         (int)smem2);

    attn_kernel<<<R_LEN, 256, smem1>>>(M, mask, lng, lnb, Wq, Wk, Wv);
    out_kernel<<<dim3(R_LEN / 128, S_LEN), 256, smem2>>>(M, lng, lnb, Wg, bg, Wo, bo, out);
}